// round 5
// baseline (speedup 1.0000x reference)
#include <cuda_runtime.h>
#include <math.h>

#define NB 8
#define NH 16
#define ND 1024
#define NHD 64
#define NPAST 8192
#define NBH (NB*NH)                   // 128
#define KEYS_PER_WARP 32
#define WARPS_PB 8
#define KEYS_PB (KEYS_PER_WARP*WARPS_PB)  // 256 keys per block
#define NCHUNK (NPAST/KEYS_PB)            // 32 block-chunks per (b,h)
#define LN10000 9.210340371976184f

#define PROJ_KS 2                     // column splits for qkv projection
#define PROJ_CW (ND/PROJ_KS)          // 512 cols per chunk
#define OP_KS 4                       // column splits for output projection
#define OP_CW (ND/OP_KS)              // 256 cols per chunk

// Scratch (allocation-free: __device__ globals)
__device__ float g_qkvp[PROJ_KS][3*NB*ND];  // qkv partial sums (no bias)
__device__ float g_m[NBH*NCHUNK];
__device__ float g_l[NBH*NCHUNK];
__device__ float g_acc[NBH*NCHUNK*NHD];     // 1 MB
__device__ float g_ctx[NB*ND];
__device__ float g_op[OP_KS][NB*ND];        // outproj partial sums

// ---------------------------------------------------------------------------
// Kernel A: QKV projection, batch-amortized + split-K.
// grid (384, PROJ_KS), 256 thr.  Warp w computes the blockIdx.y-th column
// chunk of row r = bx*8+w of [Wq;Wk;Wv] for ALL 8 batches.
// ---------------------------------------------------------------------------
__global__ void proj_kernel(const float* __restrict__ x,
                            const float* __restrict__ Wq,
                            const float* __restrict__ Wk,
                            const float* __restrict__ Wv) {
    __shared__ float xs[NB*PROJ_CW];                // 16 KB
    const int ck = blockIdx.y;
    for (int i = threadIdx.x; i < NB*PROJ_CW; i += blockDim.x) {
        const int b = i / PROJ_CW, c = i % PROJ_CW;
        xs[i] = x[b*ND + ck*PROJ_CW + c];
    }
    __syncthreads();

    const int warp = threadIdx.x >> 5, lane = threadIdx.x & 31;
    const int r = blockIdx.x * 8 + warp;            // 0..3071
    const int which = r >> 10;                      // 0=q 1=k 2=v
    const int row = r & 1023;
    const float* W = (which == 0) ? Wq : (which == 1) ? Wk : Wv;

    const float4* Wr  = (const float4*)(W + (size_t)row * ND) + ck*(PROJ_CW/4);
    const float4* xs4 = (const float4*)xs;          // [NB][PROJ_CW/4]
    float acc[NB];
#pragma unroll
    for (int b = 0; b < NB; ++b) acc[b] = 0.f;

    // Preload all 4 weight quads -> 4 loads in flight, then FMA.
    float4 w4[PROJ_CW/128];
#pragma unroll
    for (int it = 0; it < PROJ_CW/128; ++it) w4[it] = Wr[it*32 + lane];
#pragma unroll
    for (int it = 0; it < PROJ_CW/128; ++it) {
#pragma unroll
        for (int b = 0; b < NB; ++b) {
            const float4 x4 = xs4[b*(PROJ_CW/4) + it*32 + lane];
            acc[b] += w4[it].x*x4.x + w4[it].y*x4.y + w4[it].z*x4.z + w4[it].w*x4.w;
        }
    }
#pragma unroll
    for (int b = 0; b < NB; ++b) {
#pragma unroll
        for (int o = 16; o; o >>= 1) acc[b] += __shfl_xor_sync(0xffffffffu, acc[b], o);
    }
    if (lane == 0) {
#pragma unroll
        for (int b = 0; b < NB; ++b)
            g_qkvp[ck][which*NB*ND + b*ND + row] = acc[b];
    }
}

// ---------------------------------------------------------------------------
// Kernel B: flash-decoding partials.  grid (NCHUNK, NBH), 256 thr (8 warps).
// q assembled from the 2 projection partials + bias, RoPE fused.
// ---------------------------------------------------------------------------
__global__ void attn_partial(const float* __restrict__ past_k,
                             const float* __restrict__ past_v,
                             const float* __restrict__ bq) {
    const int bh   = blockIdx.y;
    const int warp = threadIdx.x >> 5, lane = threadIdx.x & 31;
    const int b = bh >> 4, h = bh & 15;

    __shared__ float qs[NHD];
    __shared__ float sm_m[WARPS_PB], sm_l[WARPS_PB];
    __shared__ float sm_acc[WARPS_PB][NHD];

    if (threadIdx.x < 32) {
        const int i = threadIdx.x;                  // freq index 0..31
        const float inv = expf(-((float)(2*i) / (float)NHD) * LN10000);
        float sn, cs; sincosf((float)NPAST * inv, &sn, &cs);
        const int base = b*ND + h*NHD;
        const float q1 = g_qkvp[0][base+i]    + g_qkvp[1][base+i]    + bq[h*NHD+i];
        const float q2 = g_qkvp[0][base+i+32] + g_qkvp[1][base+i+32] + bq[h*NHD+i+32];
        qs[i]    = q1*cs - q2*sn;
        qs[i+32] = q2*cs + q1*sn;
    }
    __syncthreads();

    const int l16 = lane & 15;
    const float4 q4 = ((const float4*)qs)[l16];

    const int wchunk = blockIdx.x * WARPS_PB + warp;   // 0..255
    const size_t off = ((size_t)bh * NPAST + (size_t)wchunk * KEYS_PER_WARP) * NHD;
    const float4* kb = (const float4*)(past_k + off);
    const float4* vb = (const float4*)(past_v + off);

    float m = -1e30f, l = 0.f;
    float4 acc = make_float4(0.f, 0.f, 0.f, 0.f);

#pragma unroll 4
    for (int j = 0; j < KEYS_PER_WARP/2; ++j) {
        const float4 k4 = __ldcs(kb + j*32 + lane);    // 2 key rows / warp
        const float4 v4 = __ldcs(vb + j*32 + lane);
        float s = q4.x*k4.x + q4.y*k4.y + q4.z*k4.z + q4.w*k4.w;
        s += __shfl_xor_sync(0xffffffffu, s, 1);
        s += __shfl_xor_sync(0xffffffffu, s, 2);
        s += __shfl_xor_sync(0xffffffffu, s, 4);
        s += __shfl_xor_sync(0xffffffffu, s, 8);
        s *= 0.125f;                                   // 1/sqrt(64)
        const float nm = fmaxf(m, s);
        const float f  = __expf(m - nm);
        const float p  = __expf(s - nm);
        acc.x = acc.x*f + p*v4.x;
        acc.y = acc.y*f + p*v4.y;
        acc.z = acc.z*f + p*v4.z;
        acc.w = acc.w*f + p*v4.w;
        l = l*f + p;
        m = nm;
    }

    // Merge the two half-warp streams (even keys / odd keys).
    const float mo = __shfl_xor_sync(0xffffffffu, m, 16);
    const float lo = __shfl_xor_sync(0xffffffffu, l, 16);
    float4 ao;
    ao.x = __shfl_xor_sync(0xffffffffu, acc.x, 16);
    ao.y = __shfl_xor_sync(0xffffffffu, acc.y, 16);
    ao.z = __shfl_xor_sync(0xffffffffu, acc.z, 16);
    ao.w = __shfl_xor_sync(0xffffffffu, acc.w, 16);
    const float M  = fmaxf(m, mo);
    const float wa = __expf(m - M), wb = __expf(mo - M);
    float4 comb;
    comb.x = acc.x*wa + ao.x*wb;
    comb.y = acc.y*wa + ao.y*wb;
    comb.z = acc.z*wa + ao.z*wb;
    comb.w = acc.w*wa + ao.w*wb;
    const float L = l*wa + lo*wb;

    if (lane < 16) ((float4*)sm_acc[warp])[l16] = comb;
    if (lane == 0) { sm_m[warp] = M; sm_l[warp] = L; }
    __syncthreads();

    // First 64 threads combine the 8 warp partials -> one block partial.
    if (threadIdx.x < NHD) {
        const int d = threadIdx.x;
        float Mb = sm_m[0];
#pragma unroll
        for (int w = 1; w < WARPS_PB; ++w) Mb = fmaxf(Mb, sm_m[w]);
        float Lb = 0.f, a = 0.f;
#pragma unroll
        for (int w = 0; w < WARPS_PB; ++w) {
            const float wg = __expf(sm_m[w] - Mb);
            a  += sm_acc[w][d] * wg;
            Lb += sm_l[w] * wg;
        }
        const int idx = bh*NCHUNK + blockIdx.x;
        g_acc[idx*NHD + d] = a;
        if (d == 0) { g_m[idx] = Mb; g_l[idx] = Lb; }
    }
}

// ---------------------------------------------------------------------------
// Kernel C: combine 32 block partials per (b,h) + fold in the new key/value
// (assembled from projection partials + bias, RoPE(k_new) fused).
// grid NBH, 256 thr.
// ---------------------------------------------------------------------------
__global__ void attn_reduce(const float* __restrict__ bq,
                            const float* __restrict__ bk,
                            const float* __restrict__ bv) {
    const int bh  = blockIdx.x;
    const int tid = threadIdx.x;
    const int c = tid >> 6, d = tid & 63;
    const int b = bh >> 4, h = bh & 15;

    __shared__ float qs[NHD], ks[NHD];
    __shared__ float s_acc[4][NHD];
    __shared__ float s_l[4];
    __shared__ float red[NHD];
    __shared__ float s_dot;

    if (tid < 32) {
        const int i = tid;
        const float inv = expf(-((float)(2*i) / (float)NHD) * LN10000);
        float sn, cs; sincosf((float)NPAST * inv, &sn, &cs);
        const int qb = b*ND + h*NHD;
        const int kb_ = NB*ND + b*ND + h*NHD;
        const float q1 = g_qkvp[0][qb+i]     + g_qkvp[1][qb+i]     + bq[h*NHD+i];
        const float q2 = g_qkvp[0][qb+i+32]  + g_qkvp[1][qb+i+32]  + bq[h*NHD+i+32];
        qs[i]    = q1*cs - q2*sn;
        qs[i+32] = q2*cs + q1*sn;
        const float k1 = g_qkvp[0][kb_+i]    + g_qkvp[1][kb_+i]    + bk[h*NHD+i];
        const float k2 = g_qkvp[0][kb_+i+32] + g_qkvp[1][kb_+i+32] + bk[h*NHD+i+32];
        ks[i]    = k1*cs - k2*sn;
        ks[i+32] = k2*cs + k1*sn;
    }
    __syncthreads();

    const float* mptr = g_m + bh*NCHUNK;
    const float* lptr = g_l + bh*NCHUNK;
    const float* aptr = g_acc + (size_t)bh*NCHUNK*NHD;

    float M = -1e30f;
#pragma unroll
    for (int i = 0; i < NCHUNK; ++i) M = fmaxf(M, mptr[i]);

    float L = 0.f, a = 0.f;
#pragma unroll
    for (int i = c; i < NCHUNK; i += 4) {
        const float w = __expf(mptr[i] - M);
        L += lptr[i] * w;
        a += aptr[i*NHD + d] * w;
    }
    s_acc[c][d] = a;
    if (d == 0) s_l[c] = L;

    if (tid < NHD) red[tid] = qs[tid] * ks[tid];
    __syncthreads();

    if (tid < 32) {
        float v = red[tid] + red[tid + 32];
#pragma unroll
        for (int o = 16; o; o >>= 1) v += __shfl_xor_sync(0xffffffffu, v, o);
        if (tid == 0) s_dot = v * 0.125f;          // score of the new key
    }
    __syncthreads();

    if (tid < NHD) {
        float A  = s_acc[0][d] + s_acc[1][d] + s_acc[2][d] + s_acc[3][d];
        float Lt = s_l[0] + s_l[1] + s_l[2] + s_l[3];
        const int vb_ = 2*NB*ND + b*ND + h*NHD + d;
        const float vd = g_qkvp[0][vb_] + g_qkvp[1][vb_] + bv[h*NHD + d];
        const float s_new = s_dot;
        const float M2 = fmaxf(M, s_new);
        const float w0 = __expf(M - M2);
        const float p  = __expf(s_new - M2);
        A  = A*w0 + p*vd;
        Lt = Lt*w0 + p;
        g_ctx[b*ND + h*NHD + d] = A / Lt;
    }
}

// ---------------------------------------------------------------------------
// Kernel D: output projection, batch-amortized + split-K.
// grid (128, OP_KS), 256 thr.  Partial sums to g_op.
// ---------------------------------------------------------------------------
__global__ void outproj_kernel(const float* __restrict__ Wo) {
    __shared__ float cs[NB*OP_CW];                  // 8 KB
    const int ck = blockIdx.y;
    for (int i = threadIdx.x; i < NB*OP_CW; i += blockDim.x) {
        const int b = i / OP_CW, c = i % OP_CW;
        cs[i] = g_ctx[b*ND + ck*OP_CW + c];
    }
    __syncthreads();

    const int warp = threadIdx.x >> 5, lane = threadIdx.x & 31;
    const int r = blockIdx.x * 8 + warp;            // 0..1023
    const float4* Wr  = (const float4*)(Wo + (size_t)r * ND) + ck*(OP_CW/4);
    const float4* cs4 = (const float4*)cs;          // [NB][OP_CW/4]
    float acc[NB];
#pragma unroll
    for (int b = 0; b < NB; ++b) acc[b] = 0.f;

    float4 w4[OP_CW/128];
#pragma unroll
    for (int it = 0; it < OP_CW/128; ++it) w4[it] = Wr[it*32 + lane];
#pragma unroll
    for (int it = 0; it < OP_CW/128; ++it) {
#pragma unroll
        for (int b = 0; b < NB; ++b) {
            const float4 c4 = cs4[b*(OP_CW/4) + it*32 + lane];
            acc[b] += w4[it].x*c4.x + w4[it].y*c4.y + w4[it].z*c4.z + w4[it].w*c4.w;
        }
    }
#pragma unroll
    for (int b = 0; b < NB; ++b) {
#pragma unroll
        for (int o = 16; o; o >>= 1) acc[b] += __shfl_xor_sync(0xffffffffu, acc[b], o);
    }
    if (lane == 0) {
#pragma unroll
        for (int b = 0; b < NB; ++b) g_op[ck][b*ND + r] = acc[b];
    }
}

// ---------------------------------------------------------------------------
// Kernel E: combine outproj partials + bias -> out.  8192 threads.
// ---------------------------------------------------------------------------
__global__ void outcombine_kernel(const float* __restrict__ bo,
                                  float* __restrict__ out) {
    const int i = blockIdx.x * blockDim.x + threadIdx.x;
    if (i >= NB*ND) return;
    float v = bo[i & (ND-1)];
#pragma unroll
    for (int k = 0; k < OP_KS; ++k) v += g_op[k][i];
    out[i] = v;
}

// ---------------------------------------------------------------------------
extern "C" void kernel_launch(void* const* d_in, const int* in_sizes, int n_in,
                              void* d_out, int out_size) {
    const float* x      = (const float*)d_in[0];
    const float* Wq     = (const float*)d_in[1];
    const float* bq     = (const float*)d_in[2];
    const float* Wk     = (const float*)d_in[3];
    const float* bk     = (const float*)d_in[4];
    const float* Wv     = (const float*)d_in[5];
    const float* bv     = (const float*)d_in[6];
    const float* Wo     = (const float*)d_in[7];
    const float* bo     = (const float*)d_in[8];
    const float* past_k = (const float*)d_in[9];
    const float* past_v = (const float*)d_in[10];
    float* out = (float*)d_out;

    proj_kernel<<<dim3(3*ND/8, PROJ_KS), 256>>>(x, Wq, Wk, Wv);
    attn_partial<<<dim3(NCHUNK, NBH), 256>>>(past_k, past_v, bq);
    attn_reduce<<<NBH, 256>>>(bq, bk, bv);
    outproj_kernel<<<dim3(ND/8, OP_KS), 256>>>(Wo);
    outcombine_kernel<<<(NB*ND + 255)/256, 256>>>(bo, out);
}

// round 6
// speedup vs baseline: 1.0289x; 1.0289x over previous
#include <cuda_runtime.h>
#include <math.h>

#define NB 8
#define NH 16
#define ND 1024
#define NHD 64
#define NPAST 8192
#define NBH (NB*NH)                   // 128
#define KEYS_PER_WARP 32
#define WARPS_PB 8
#define KEYS_PB (KEYS_PER_WARP*WARPS_PB)  // 256 keys per block
#define NCHUNK (NPAST/KEYS_PB)            // 32 block-chunks per (b,h)
#define LN10000 9.210340371976184f

// Scratch (allocation-free: __device__ globals)
__device__ float g_qkv[3*NB*ND];            // q | k_new | v_new (bias applied)
__device__ float g_m[NBH*NCHUNK];
__device__ float g_l[NBH*NCHUNK];
__device__ float g_acc[NBH*NCHUNK*NHD];     // 1 MB
__device__ float g_ctx[NB*ND];

// ---------------------------------------------------------------------------
// Kernel A: QKV projection, block-per-row.  grid 3072, 256 thr.
// Block computes one output row of [Wq;Wk;Wv] for ALL 8 batches: every thread
// issues exactly one float4 weight load (max MLP), 8 batch accumulators,
// then a warp-shuffle + smem block reduction.
// ---------------------------------------------------------------------------
__global__ void proj_kernel(const float* __restrict__ x,
                            const float* __restrict__ Wq, const float* __restrict__ bq,
                            const float* __restrict__ Wk, const float* __restrict__ bk,
                            const float* __restrict__ Wv, const float* __restrict__ bv) {
    const int r = blockIdx.x;                       // 0..3071
    const int which = r >> 10;                      // 0=q 1=k 2=v
    const int row = r & 1023;
    const float* W; const float* bias;
    if (which == 0)      { W = Wq; bias = bq; }
    else if (which == 1) { W = Wk; bias = bk; }
    else                 { W = Wv; bias = bv; }

    const int warp = threadIdx.x >> 5, lane = threadIdx.x & 31;
    const int c4 = warp*32 + lane;                  // float4 col 0..255

    const float4 w4 = ((const float4*)(W + (size_t)row * ND))[c4];
    const float4* x4p = (const float4*)x;

    float acc[NB];
#pragma unroll
    for (int b = 0; b < NB; ++b) {
        const float4 x4 = __ldg(x4p + b*(ND/4) + c4);
        acc[b] = w4.x*x4.x + w4.y*x4.y + w4.z*x4.z + w4.w*x4.w;
    }
#pragma unroll
    for (int b = 0; b < NB; ++b) {
#pragma unroll
        for (int o = 16; o; o >>= 1) acc[b] += __shfl_xor_sync(0xffffffffu, acc[b], o);
    }

    __shared__ float sm[8][NB+1];
    if (lane == 0) {
#pragma unroll
        for (int b = 0; b < NB; ++b) sm[warp][b] = acc[b];
    }
    __syncthreads();
    if (threadIdx.x < NB) {
        const int b = threadIdx.x;
        float v = sm[0][b];
#pragma unroll
        for (int w = 1; w < 8; ++w) v += sm[w][b];
        g_qkv[which*NB*ND + b*ND + row] = v + bias[row];
    }
}

// ---------------------------------------------------------------------------
// Kernel B: flash-decoding partials.  grid (NCHUNK, NBH), 256 thr (8 warps).
// RoPE(q) fused.  float4 loads: lanes 0-15 own key 2j, lanes 16-31 key 2j+1.
// ---------------------------------------------------------------------------
__global__ void attn_partial(const float* __restrict__ past_k,
                             const float* __restrict__ past_v) {
    const int bh   = blockIdx.y;
    const int warp = threadIdx.x >> 5, lane = threadIdx.x & 31;
    const int b = bh >> 4, h = bh & 15;

    __shared__ float qs[NHD];
    __shared__ float sm_m[WARPS_PB], sm_l[WARPS_PB];
    __shared__ float sm_acc[WARPS_PB][NHD];

    if (threadIdx.x < 32) {
        const int i = threadIdx.x;                  // freq index 0..31
        const float inv = expf(-((float)(2*i) / (float)NHD) * LN10000);
        float sn, cs; sincosf((float)NPAST * inv, &sn, &cs);
        const float* gq = g_qkv + b*ND + h*NHD;
        const float q1 = gq[i], q2 = gq[i+32];
        qs[i]    = q1*cs - q2*sn;
        qs[i+32] = q2*cs + q1*sn;
    }
    __syncthreads();

    const int l16 = lane & 15;
    const float4 q4 = ((const float4*)qs)[l16];

    const int wchunk = blockIdx.x * WARPS_PB + warp;   // 0..255
    const size_t off = ((size_t)bh * NPAST + (size_t)wchunk * KEYS_PER_WARP) * NHD;
    const float4* kb = (const float4*)(past_k + off);
    const float4* vb = (const float4*)(past_v + off);

    float m = -1e30f, l = 0.f;
    float4 acc = make_float4(0.f, 0.f, 0.f, 0.f);

#pragma unroll 4
    for (int j = 0; j < KEYS_PER_WARP/2; ++j) {
        const float4 k4 = __ldcs(kb + j*32 + lane);    // 2 key rows / warp
        const float4 v4 = __ldcs(vb + j*32 + lane);
        float s = q4.x*k4.x + q4.y*k4.y + q4.z*k4.z + q4.w*k4.w;
        s += __shfl_xor_sync(0xffffffffu, s, 1);
        s += __shfl_xor_sync(0xffffffffu, s, 2);
        s += __shfl_xor_sync(0xffffffffu, s, 4);
        s += __shfl_xor_sync(0xffffffffu, s, 8);
        s *= 0.125f;                                   // 1/sqrt(64)
        const float nm = fmaxf(m, s);
        const float f  = __expf(m - nm);
        const float p  = __expf(s - nm);
        acc.x = acc.x*f + p*v4.x;
        acc.y = acc.y*f + p*v4.y;
        acc.z = acc.z*f + p*v4.z;
        acc.w = acc.w*f + p*v4.w;
        l = l*f + p;
        m = nm;
    }

    // Merge the two half-warp streams (even keys / odd keys).
    const float mo = __shfl_xor_sync(0xffffffffu, m, 16);
    const float lo = __shfl_xor_sync(0xffffffffu, l, 16);
    float4 ao;
    ao.x = __shfl_xor_sync(0xffffffffu, acc.x, 16);
    ao.y = __shfl_xor_sync(0xffffffffu, acc.y, 16);
    ao.z = __shfl_xor_sync(0xffffffffu, acc.z, 16);
    ao.w = __shfl_xor_sync(0xffffffffu, acc.w, 16);
    const float M  = fmaxf(m, mo);
    const float wa = __expf(m - M), wb = __expf(mo - M);
    float4 comb;
    comb.x = acc.x*wa + ao.x*wb;
    comb.y = acc.y*wa + ao.y*wb;
    comb.z = acc.z*wa + ao.z*wb;
    comb.w = acc.w*wa + ao.w*wb;
    const float L = l*wa + lo*wb;

    if (lane < 16) ((float4*)sm_acc[warp])[l16] = comb;
    if (lane == 0) { sm_m[warp] = M; sm_l[warp] = L; }
    __syncthreads();

    // First 64 threads combine the 8 warp partials -> one block partial.
    if (threadIdx.x < NHD) {
        const int d = threadIdx.x;
        float Mb = sm_m[0];
#pragma unroll
        for (int w = 1; w < WARPS_PB; ++w) Mb = fmaxf(Mb, sm_m[w]);
        float Lb = 0.f, a = 0.f;
#pragma unroll
        for (int w = 0; w < WARPS_PB; ++w) {
            const float wg = __expf(sm_m[w] - Mb);
            a  += sm_acc[w][d] * wg;
            Lb += sm_l[w] * wg;
        }
        const int idx = bh*NCHUNK + blockIdx.x;
        g_acc[idx*NHD + d] = a;
        if (d == 0) { g_m[idx] = Mb; g_l[idx] = Lb; }
    }
}

// ---------------------------------------------------------------------------
// Kernel C: combine 32 block partials per (b,h) + fold in the new key/value
// (RoPE(k_new) fused).  grid NBH, 256 thr.
// ---------------------------------------------------------------------------
__global__ void attn_reduce() {
    const int bh  = blockIdx.x;
    const int tid = threadIdx.x;
    const int c = tid >> 6, d = tid & 63;
    const int b = bh >> 4, h = bh & 15;

    __shared__ float qs[NHD], ks[NHD];
    __shared__ float s_acc[4][NHD];
    __shared__ float s_l[4];
    __shared__ float red[NHD];
    __shared__ float s_dot;

    if (tid < 32) {
        const int i = tid;
        const float inv = expf(-((float)(2*i) / (float)NHD) * LN10000);
        float sn, cs; sincosf((float)NPAST * inv, &sn, &cs);
        const float* gq = g_qkv + b*ND + h*NHD;
        const float* gk = g_qkv + NB*ND + b*ND + h*NHD;
        const float q1 = gq[i], q2 = gq[i+32];
        qs[i]    = q1*cs - q2*sn;
        qs[i+32] = q2*cs + q1*sn;
        const float k1 = gk[i], k2 = gk[i+32];
        ks[i]    = k1*cs - k2*sn;
        ks[i+32] = k2*cs + k1*sn;
    }
    __syncthreads();

    const float* mptr = g_m + bh*NCHUNK;
    const float* lptr = g_l + bh*NCHUNK;
    const float* aptr = g_acc + (size_t)bh*NCHUNK*NHD;

    float M = -1e30f;
#pragma unroll
    for (int i = 0; i < NCHUNK; ++i) M = fmaxf(M, mptr[i]);

    float L = 0.f, a = 0.f;
#pragma unroll
    for (int i = c; i < NCHUNK; i += 4) {
        const float w = __expf(mptr[i] - M);
        L += lptr[i] * w;
        a += aptr[i*NHD + d] * w;
    }
    s_acc[c][d] = a;
    if (d == 0) s_l[c] = L;

    if (tid < NHD) red[tid] = qs[tid] * ks[tid];
    __syncthreads();

    if (tid < 32) {
        float v = red[tid] + red[tid + 32];
#pragma unroll
        for (int o = 16; o; o >>= 1) v += __shfl_xor_sync(0xffffffffu, v, o);
        if (tid == 0) s_dot = v * 0.125f;          // score of the new key
    }
    __syncthreads();

    if (tid < NHD) {
        float A  = s_acc[0][d] + s_acc[1][d] + s_acc[2][d] + s_acc[3][d];
        float Lt = s_l[0] + s_l[1] + s_l[2] + s_l[3];
        const float s_new = s_dot;
        const float M2 = fmaxf(M, s_new);
        const float w0 = __expf(M - M2);
        const float p  = __expf(s_new - M2);
        const float vd = g_qkv[2*NB*ND + b*ND + h*NHD + d];
        A  = A*w0 + p*vd;
        Lt = Lt*w0 + p;
        g_ctx[b*ND + h*NHD + d] = A / Lt;
    }
}

// ---------------------------------------------------------------------------
// Kernel D: output projection, block-per-row.  grid 1024, 256 thr.
// One float4 Wo load per thread, 8 batch accumulators, block reduce.
// ---------------------------------------------------------------------------
__global__ void outproj_kernel(const float* __restrict__ Wo,
                               const float* __restrict__ bo,
                               float* __restrict__ out) {
    const int r = blockIdx.x;                       // 0..1023
    const int warp = threadIdx.x >> 5, lane = threadIdx.x & 31;
    const int c4 = warp*32 + lane;                  // float4 col 0..255

    const float4 w4 = ((const float4*)(Wo + (size_t)r * ND))[c4];
    const float4* cp = (const float4*)g_ctx;

    float acc[NB];
#pragma unroll
    for (int b = 0; b < NB; ++b) {
        const float4 c4v = cp[b*(ND/4) + c4];
        acc[b] = w4.x*c4v.x + w4.y*c4v.y + w4.z*c4v.z + w4.w*c4v.w;
    }
#pragma unroll
    for (int b = 0; b < NB; ++b) {
#pragma unroll
        for (int o = 16; o; o >>= 1) acc[b] += __shfl_xor_sync(0xffffffffu, acc[b], o);
    }

    __shared__ float sm[8][NB+1];
    if (lane == 0) {
#pragma unroll
        for (int b = 0; b < NB; ++b) sm[warp][b] = acc[b];
    }
    __syncthreads();
    if (threadIdx.x < NB) {
        const int b = threadIdx.x;
        float v = sm[0][b];
#pragma unroll
        for (int w = 1; w < 8; ++w) v += sm[w][b];
        out[b*ND + r] = v + bo[r];
    }
}

// ---------------------------------------------------------------------------
extern "C" void kernel_launch(void* const* d_in, const int* in_sizes, int n_in,
                              void* d_out, int out_size) {
    const float* x      = (const float*)d_in[0];
    const float* Wq     = (const float*)d_in[1];
    const float* bq     = (const float*)d_in[2];
    const float* Wk     = (const float*)d_in[3];
    const float* bk     = (const float*)d_in[4];
    const float* Wv     = (const float*)d_in[5];
    const float* bv     = (const float*)d_in[6];
    const float* Wo     = (const float*)d_in[7];
    const float* bo     = (const float*)d_in[8];
    const float* past_k = (const float*)d_in[9];
    const float* past_v = (const float*)d_in[10];
    float* out = (float*)d_out;

    proj_kernel<<<3*ND, 256>>>(x, Wq, bq, Wk, bk, Wv, bv);
    attn_partial<<<dim3(NCHUNK, NBH), 256>>>(past_k, past_v);
    attn_reduce<<<NBH, 256>>>();
    outproj_kernel<<<ND, 256>>>(Wo, bo, out);
}